// round 3
// baseline (speedup 1.0000x reference)
#include <cuda_runtime.h>

// Problem constants
#define B_ 4
#define T_ 2048
#define C_ 1024
#define H_ 16
#define D_ 64
#define M_ (B_ * T_)   // 8192 rows in all GEMMs

// Scratch: __device__ globals (no allocation allowed in kernel_launch)
__device__ float g_q[(size_t)B_ * H_ * T_ * D_];   // [B,H,T,D]
__device__ float g_k[(size_t)B_ * H_ * T_ * D_];
__device__ float g_v[(size_t)B_ * H_ * T_ * D_];
__device__ float g_y[(size_t)B_ * T_ * C_];        // [B,T,C] attention output

// ---------------------------------------------------------------------------
// 128x128x8 register-blocked SGEMM body with software-pipelined global loads:
// out = A[M,K] @ W[K,N] + bias
// qkv_layout=1 -> scatter into [B,H,T,D]; else plain [M,N] row-major.
// 256 threads, each computes an 8x8 micro-tile.
// ---------------------------------------------------------------------------
__device__ __forceinline__ void gemm_body(
    const float* __restrict__ A, const float* __restrict__ W,
    const float* __restrict__ bias, float* __restrict__ out, int qkv_layout)
{
    __shared__ float As[8][128];   // A tile transposed: As[k][m]
    __shared__ float Bs[8][128];   // Bs[k][n]

    const int tid = threadIdx.x;           // 0..255
    const int m0  = blockIdx.y * 128;
    const int n0  = blockIdx.x * 128;

    // cooperative load mapping (float4)
    const int aRow = tid >> 1;             // 0..127
    const int aCol = (tid & 1) * 4;        // 0 or 4
    const int bRow = tid >> 5;             // 0..7
    const int bCol = (tid & 31) * 4;       // 0..124

    const int ty = tid >> 4;               // 0..15 -> row group
    const int tx = tid & 15;               // 0..15 -> col group

    const float* aPtr = A + (size_t)(m0 + aRow) * C_ + aCol;
    const float* bPtr = W + (size_t)bRow * C_ + n0 + bCol;

    float acc[8][8];
    #pragma unroll
    for (int i = 0; i < 8; i++)
        #pragma unroll
        for (int j = 0; j < 8; j++) acc[i][j] = 0.f;

    // prologue: fetch first tiles into registers
    float4 av = *(const float4*)(aPtr);
    float4 bv = *(const float4*)(bPtr);

    for (int k0 = 0; k0 < C_; k0 += 8) {
        // stage current registers into SMEM
        As[aCol + 0][aRow] = av.x;
        As[aCol + 1][aRow] = av.y;
        As[aCol + 2][aRow] = av.z;
        As[aCol + 3][aRow] = av.w;
        *(float4*)(&Bs[bRow][bCol]) = bv;
        __syncthreads();

        // prefetch next tiles while FMAs run on current SMEM tile
        if (k0 + 8 < C_) {
            av = *(const float4*)(aPtr + k0 + 8);
            bv = *(const float4*)(bPtr + (size_t)(k0 + 8) * C_);
        }

        #pragma unroll
        for (int kk = 0; kk < 8; kk++) {
            float ra[8], rb[8];
            *(float4*)&ra[0] = *(const float4*)&As[kk][ty * 8];
            *(float4*)&ra[4] = *(const float4*)&As[kk][ty * 8 + 4];
            *(float4*)&rb[0] = *(const float4*)&Bs[kk][tx * 8];
            *(float4*)&rb[4] = *(const float4*)&Bs[kk][tx * 8 + 4];
            #pragma unroll
            for (int i = 0; i < 8; i++)
                #pragma unroll
                for (int j = 0; j < 8; j++)
                    acc[i][j] += ra[i] * rb[j];
        }
        __syncthreads();
    }

    #pragma unroll
    for (int i = 0; i < 8; i++) {
        const int m = m0 + ty * 8 + i;
        const int b = m >> 11;            // /T_
        const int t = m & (T_ - 1);
        #pragma unroll
        for (int j = 0; j < 8; j++) {
            const int n = n0 + tx * 8 + j;
            const float val = acc[i][j] + bias[n];
            if (qkv_layout) {
                const int h = n >> 6;     // /D_
                const int d = n & (D_ - 1);
                out[(((size_t)(b * H_ + h) * T_ + t) * D_) + d] = val;
            } else {
                out[(size_t)m * C_ + n] = val;
            }
        }
    }
}

// QKV projections: blockIdx.z selects which of Wq/Wk/Wv to apply.
__global__ __launch_bounds__(256)
void qkv_gemm_kernel(const float* __restrict__ x,
                     const float* __restrict__ Wq, const float* __restrict__ bq,
                     const float* __restrict__ Wk, const float* __restrict__ bk,
                     const float* __restrict__ Wv, const float* __restrict__ bv)
{
    const float* W; const float* bias; float* out;
    if (blockIdx.z == 0)      { W = Wq; bias = bq; out = g_q; }
    else if (blockIdx.z == 1) { W = Wk; bias = bk; out = g_k; }
    else                      { W = Wv; bias = bv; out = g_v; }
    gemm_body(x, W, bias, out, 1);
}

// Output projection: d_out = g_y @ Wp + bp
__global__ __launch_bounds__(256)
void proj_gemm_kernel(const float* __restrict__ Wp, const float* __restrict__ bp,
                      float* __restrict__ out)
{
    gemm_body(g_y, Wp, bp, out, 0);
}

// ---------------------------------------------------------------------------
// Causal flash attention (fp32). One block = 128 query rows of one (b,h).
// Each thread owns one query row: q[64] and o[64] in registers.
// K/V tiles (32 keys) staged in SMEM; reads are warp-uniform broadcasts.
// ---------------------------------------------------------------------------
__global__ __launch_bounds__(128)
void flash_kernel()
{
    __shared__ float Kt[32][64];
    __shared__ float Vt[32][64];
    __shared__ float S[128][33];   // padded row stride: conflict-free

    const int bh  = blockIdx.y;            // 0..B*H-1
    const int qi  = blockIdx.x;            // query tile 0..15
    const int tid = threadIdx.x;           // 0..127
    const int row = qi * 128 + tid;

    const float* Qb = g_q + (size_t)bh * T_ * D_;
    const float* Kb = g_k + (size_t)bh * T_ * D_;
    const float* Vb = g_v + (size_t)bh * T_ * D_;

    const float scale = 0.125f;            // 1/sqrt(64)
    float q[64];
    #pragma unroll
    for (int d4 = 0; d4 < 16; d4++) {
        float4 t = *(const float4*)&Qb[(size_t)row * D_ + d4 * 4];
        q[d4 * 4 + 0] = t.x * scale;
        q[d4 * 4 + 1] = t.y * scale;
        q[d4 * 4 + 2] = t.z * scale;
        q[d4 * 4 + 3] = t.w * scale;
    }

    float o[64];
    #pragma unroll
    for (int d = 0; d < 64; d++) o[d] = 0.f;
    float mrun = -1e30f, l = 0.f;

    const int ntile = 4 * (qi + 1);        // key tiles of 32 covering keys <= max row
    const int full  = (qi * 128) / 32;     // tiles fully below the diagonal for ALL rows

    for (int jt = 0; jt < ntile; jt++) {
        const int base = jt * 32;
        // cooperative K/V tile load: 512 float4 each, 128 threads x 4
        #pragma unroll
        for (int i = 0; i < 4; i++) {
            const int e = tid + i * 128;       // float4 index 0..511
            const int r = e >> 4;
            const int c = (e & 15) * 4;
            *(float4*)&Kt[r][c] = *(const float4*)&Kb[(size_t)(base + r) * D_ + c];
            *(float4*)&Vt[r][c] = *(const float4*)&Vb[(size_t)(base + r) * D_ + c];
        }
        __syncthreads();

        const bool needMask = (jt >= full);

        // scores for this tile (4-way accumulator ILP)
        float tmax = -1e30f;
        #pragma unroll 4
        for (int s = 0; s < 32; s++) {
            const float* kr = &Kt[s][0];
            float a0 = 0.f, a1 = 0.f, a2 = 0.f, a3 = 0.f;
            #pragma unroll
            for (int d = 0; d < 64; d += 4) {
                a0 += q[d + 0] * kr[d + 0];
                a1 += q[d + 1] * kr[d + 1];
                a2 += q[d + 2] * kr[d + 2];
                a3 += q[d + 3] * kr[d + 3];
            }
            float sc = (a0 + a1) + (a2 + a3);
            if (needMask) sc = (base + s <= row) ? sc : -1e30f;
            S[tid][s] = sc;
            tmax = fmaxf(tmax, sc);
        }

        // online softmax update
        const float mnew = fmaxf(mrun, tmax);
        const float corr = __expf(mrun - mnew);
        l *= corr;
        #pragma unroll
        for (int d = 0; d < 64; d++) o[d] *= corr;
        #pragma unroll 8
        for (int s = 0; s < 32; s++) {
            const float p = __expf(S[tid][s] - mnew);
            S[tid][s] = p;
            l += p;
        }
        mrun = mnew;

        // P @ V accumulate
        #pragma unroll 2
        for (int s = 0; s < 32; s++) {
            const float p = S[tid][s];
            const float* vr = &Vt[s][0];
            #pragma unroll
            for (int d = 0; d < 64; d++) o[d] += p * vr[d];
        }
        __syncthreads();
    }

    const float inv = 1.f / l;
    const int b = bh >> 4;                 // /H_
    const int h = bh & (H_ - 1);
    float* yo = g_y + ((size_t)(b * T_ + row)) * C_ + h * D_;
    #pragma unroll
    for (int d = 0; d < 64; d += 4) {
        float4 t;
        t.x = o[d + 0] * inv;
        t.y = o[d + 1] * inv;
        t.z = o[d + 2] * inv;
        t.w = o[d + 3] * inv;
        *(float4*)&yo[d] = t;
    }
}

// ---------------------------------------------------------------------------
extern "C" void kernel_launch(void* const* d_in, const int* in_sizes, int n_in,
                              void* d_out, int out_size)
{
    const float* x  = (const float*)d_in[0];
    const float* Wq = (const float*)d_in[1];
    const float* bq = (const float*)d_in[2];
    const float* Wk = (const float*)d_in[3];
    const float* bk = (const float*)d_in[4];
    const float* Wv = (const float*)d_in[5];
    const float* bv = (const float*)d_in[6];
    const float* Wp = (const float*)d_in[7];
    const float* bp = (const float*)d_in[8];
    float* out = (float*)d_out;

    dim3 gq(C_ / 128, M_ / 128, 3);        // (8, 64, 3)
    qkv_gemm_kernel<<<gq, 256>>>(x, Wq, bq, Wk, bk, Wv, bv);

    dim3 gf(T_ / 128, B_ * H_);            // (16, 64)
    flash_kernel<<<gf, 128>>>();

    dim3 gp(C_ / 128, M_ / 128);           // (8, 64)
    proj_gemm_kernel<<<gp, 256>>>(Wp, bp, out);
}

// round 4
// speedup vs baseline: 1.5051x; 1.5051x over previous
#include <cuda_runtime.h>
#include <cstdint>

// Problem constants
#define B_ 4
#define T_ 2048
#define C_ 1024
#define H_ 16
#define D_ 64
#define M_ (B_ * T_)   // 8192 rows in all GEMMs

// Scratch: __device__ globals (no allocation allowed in kernel_launch)
__device__ float g_q[(size_t)B_ * H_ * T_ * D_];   // [B,H,T,D]
__device__ float g_k[(size_t)B_ * H_ * T_ * D_];
__device__ float g_v[(size_t)B_ * H_ * T_ * D_];
__device__ float g_y[(size_t)B_ * T_ * C_];        // [B,T,C] attention output

// ---------------------------------------------------------------------------
// tf32 helpers
// ---------------------------------------------------------------------------
__device__ __forceinline__ uint32_t f2tf32(float f) {
    uint32_t u;
    asm("cvt.rna.tf32.f32 %0, %1;" : "=r"(u) : "f"(f));
    return u;
}

__device__ __forceinline__ void mma_tf32_16x8x8(
    float* d, const uint32_t* a, const uint32_t* b, const float* c)
{
    asm volatile(
        "mma.sync.aligned.m16n8k8.row.col.f32.tf32.tf32.f32 "
        "{%0,%1,%2,%3}, {%4,%5,%6,%7}, {%8,%9}, {%10,%11,%12,%13};"
        : "=f"(d[0]), "=f"(d[1]), "=f"(d[2]), "=f"(d[3])
        : "r"(a[0]), "r"(a[1]), "r"(a[2]), "r"(a[3]),
          "r"(b[0]), "r"(b[1]),
          "f"(c[0]), "f"(c[1]), "f"(c[2]), "f"(c[3]));
}

// ---------------------------------------------------------------------------
// Tensor-core tf32 GEMM: out = A[M,1024] @ W[1024,N tile] + bias
// CTA tile 128x128, K-step 32. 256 threads = 8 warps, warp tile 64x32
// (warp grid 2m x 4n; per warp 4x4 m16n8k8 fragments).
// qkv_layout=1 -> scatter into [B,H,T,D]; else plain [M,N] row-major.
// ---------------------------------------------------------------------------
#define AS_STRIDE 36   // pad: fragment loads hit 32 distinct banks
#define BS_STRIDE 132  // pad: <=2-way conflicts on B fragment loads

__device__ __forceinline__ void gemm_body_tc(
    const float* __restrict__ A, const float* __restrict__ W,
    const float* __restrict__ bias, float* __restrict__ out, int qkv_layout)
{
    __shared__ uint32_t As[128][AS_STRIDE];   // [m][k] tf32 bits
    __shared__ uint32_t Bs[32][BS_STRIDE];    // [k][n] tf32 bits

    const int tid  = threadIdx.x;         // 0..255
    const int wid  = tid >> 5;            // 0..7
    const int lane = tid & 31;
    const int g    = lane >> 2;           // group 0..7
    const int tg   = lane & 3;            // thread-in-group 0..3

    const int m0 = blockIdx.y * 128;
    const int n0 = blockIdx.x * 128;
    const int wm = (wid >> 2) * 64;       // warp m offset in tile (0/64)
    const int wn = (wid & 3) * 32;        // warp n offset in tile (0..96)

    float acc[4][4][4];
    #pragma unroll
    for (int i = 0; i < 4; i++)
        #pragma unroll
        for (int j = 0; j < 4; j++)
            #pragma unroll
            for (int r = 0; r < 4; r++) acc[i][j][r] = 0.f;

    // global-load mapping: 4 float4 per thread per tile for each of A and B
    // A tile 128(m) x 32(k):  e = tid + i*256; m = e>>3, k4 = (e&7)*4
    // B tile  32(k) x 128(n): e = tid + i*256; k = e>>5, n4 = (e&31)*4
    float4 avr[4], bvr[4];
    #pragma unroll
    for (int i = 0; i < 4; i++) {
        const int eA = tid + i * 256;
        avr[i] = *(const float4*)(A + (size_t)(m0 + (eA >> 3)) * C_ + ((eA & 7) * 4));
        const int eB = tid + i * 256;
        bvr[i] = *(const float4*)(W + (size_t)(eB >> 5) * C_ + n0 + (eB & 31) * 4);
    }

    for (int k0 = 0; k0 < C_; k0 += 32) {
        // stage prefetched registers into SMEM (converted to tf32)
        #pragma unroll
        for (int i = 0; i < 4; i++) {
            const int eA = tid + i * 256;
            const int m  = eA >> 3;
            const int k4 = (eA & 7) * 4;
            As[m][k4 + 0] = f2tf32(avr[i].x);
            As[m][k4 + 1] = f2tf32(avr[i].y);
            As[m][k4 + 2] = f2tf32(avr[i].z);
            As[m][k4 + 3] = f2tf32(avr[i].w);
            const int eB = tid + i * 256;
            const int k  = eB >> 5;
            const int n4 = (eB & 31) * 4;
            Bs[k][n4 + 0] = f2tf32(bvr[i].x);
            Bs[k][n4 + 1] = f2tf32(bvr[i].y);
            Bs[k][n4 + 2] = f2tf32(bvr[i].z);
            Bs[k][n4 + 3] = f2tf32(bvr[i].w);
        }
        __syncthreads();

        // prefetch next K-slice while MMAs run
        if (k0 + 32 < C_) {
            #pragma unroll
            for (int i = 0; i < 4; i++) {
                const int eA = tid + i * 256;
                avr[i] = *(const float4*)(A + (size_t)(m0 + (eA >> 3)) * C_
                                            + k0 + 32 + ((eA & 7) * 4));
                const int eB = tid + i * 256;
                bvr[i] = *(const float4*)(W + (size_t)(k0 + 32 + (eB >> 5)) * C_
                                            + n0 + (eB & 31) * 4);
            }
        }

        #pragma unroll
        for (int ks = 0; ks < 4; ks++) {
            const int kk = ks * 8;
            uint32_t afr[4][4], bfr[4][2];
            #pragma unroll
            for (int mf = 0; mf < 4; mf++) {
                const int row = wm + mf * 16;
                afr[mf][0] = As[row + g    ][kk + tg    ];
                afr[mf][1] = As[row + g + 8][kk + tg    ];
                afr[mf][2] = As[row + g    ][kk + tg + 4];
                afr[mf][3] = As[row + g + 8][kk + tg + 4];
            }
            #pragma unroll
            for (int nf = 0; nf < 4; nf++) {
                const int col = wn + nf * 8 + g;
                bfr[nf][0] = Bs[kk + tg    ][col];
                bfr[nf][1] = Bs[kk + tg + 4][col];
            }
            #pragma unroll
            for (int mf = 0; mf < 4; mf++)
                #pragma unroll
                for (int nf = 0; nf < 4; nf++)
                    mma_tf32_16x8x8(acc[mf][nf], afr[mf], bfr[nf], acc[mf][nf]);
        }
        __syncthreads();
    }

    // epilogue: c0=(g,2tg) c1=(g,2tg+1) c2=(g+8,2tg) c3=(g+8,2tg+1)
    #pragma unroll
    for (int mf = 0; mf < 4; mf++) {
        #pragma unroll
        for (int nf = 0; nf < 4; nf++) {
            const int col = n0 + wn + nf * 8 + 2 * tg;
            const float b0 = bias[col], b1 = bias[col + 1];
            #pragma unroll
            for (int half = 0; half < 2; half++) {
                const int m = m0 + wm + mf * 16 + g + half * 8;
                const float v0 = acc[mf][nf][half * 2 + 0] + b0;
                const float v1 = acc[mf][nf][half * 2 + 1] + b1;
                const int b = m >> 11;
                const int t = m & (T_ - 1);
                if (qkv_layout) {
                    const int h = col >> 6;
                    const int d = col & (D_ - 1);
                    float2* p = (float2*)&out[(((size_t)(b * H_ + h) * T_ + t) * D_) + d];
                    *p = make_float2(v0, v1);
                } else {
                    float2* p = (float2*)&out[(size_t)m * C_ + col];
                    *p = make_float2(v0, v1);
                }
            }
        }
    }
}

// QKV projections: blockIdx.z selects which of Wq/Wk/Wv to apply.
__global__ __launch_bounds__(256)
void qkv_gemm_kernel(const float* __restrict__ x,
                     const float* __restrict__ Wq, const float* __restrict__ bq,
                     const float* __restrict__ Wk, const float* __restrict__ bk,
                     const float* __restrict__ Wv, const float* __restrict__ bv)
{
    const float* W; const float* bias; float* out;
    if (blockIdx.z == 0)      { W = Wq; bias = bq; out = g_q; }
    else if (blockIdx.z == 1) { W = Wk; bias = bk; out = g_k; }
    else                      { W = Wv; bias = bv; out = g_v; }
    gemm_body_tc(x, W, bias, out, 1);
}

// Output projection: d_out = g_y @ Wp + bp
__global__ __launch_bounds__(256)
void proj_gemm_kernel(const float* __restrict__ Wp, const float* __restrict__ bp,
                      float* __restrict__ out)
{
    gemm_body_tc(g_y, Wp, bp, out, 0);
}

// ---------------------------------------------------------------------------
// Causal flash attention (fp32) — unchanged from R3 baseline.
// ---------------------------------------------------------------------------
__global__ __launch_bounds__(128)
void flash_kernel()
{
    __shared__ float Kt[32][64];
    __shared__ float Vt[32][64];
    __shared__ float S[128][33];

    const int bh  = blockIdx.y;
    const int qi  = blockIdx.x;
    const int tid = threadIdx.x;
    const int row = qi * 128 + tid;

    const float* Qb = g_q + (size_t)bh * T_ * D_;
    const float* Kb = g_k + (size_t)bh * T_ * D_;
    const float* Vb = g_v + (size_t)bh * T_ * D_;

    const float scale = 0.125f;
    float q[64];
    #pragma unroll
    for (int d4 = 0; d4 < 16; d4++) {
        float4 t = *(const float4*)&Qb[(size_t)row * D_ + d4 * 4];
        q[d4 * 4 + 0] = t.x * scale;
        q[d4 * 4 + 1] = t.y * scale;
        q[d4 * 4 + 2] = t.z * scale;
        q[d4 * 4 + 3] = t.w * scale;
    }

    float o[64];
    #pragma unroll
    for (int d = 0; d < 64; d++) o[d] = 0.f;
    float mrun = -1e30f, l = 0.f;

    const int ntile = 4 * (qi + 1);
    const int full  = (qi * 128) / 32;

    for (int jt = 0; jt < ntile; jt++) {
        const int base = jt * 32;
        #pragma unroll
        for (int i = 0; i < 4; i++) {
            const int e = tid + i * 128;
            const int r = e >> 4;
            const int c = (e & 15) * 4;
            *(float4*)&Kt[r][c] = *(const float4*)&Kb[(size_t)(base + r) * D_ + c];
            *(float4*)&Vt[r][c] = *(const float4*)&Vb[(size_t)(base + r) * D_ + c];
        }
        __syncthreads();

        const bool needMask = (jt >= full);

        float tmax = -1e30f;
        #pragma unroll 4
        for (int s = 0; s < 32; s++) {
            const float* kr = &Kt[s][0];
            float a0 = 0.f, a1 = 0.f, a2 = 0.f, a3 = 0.f;
            #pragma unroll
            for (int d = 0; d < 64; d += 4) {
                a0 += q[d + 0] * kr[d + 0];
                a1 += q[d + 1] * kr[d + 1];
                a2 += q[d + 2] * kr[d + 2];
                a3 += q[d + 3] * kr[d + 3];
            }
            float sc = (a0 + a1) + (a2 + a3);
            if (needMask) sc = (base + s <= row) ? sc : -1e30f;
            S[tid][s] = sc;
            tmax = fmaxf(tmax, sc);
        }

        const float mnew = fmaxf(mrun, tmax);
        const float corr = __expf(mrun - mnew);
        l *= corr;
        #pragma unroll
        for (int d = 0; d < 64; d++) o[d] *= corr;
        #pragma unroll 8
        for (int s = 0; s < 32; s++) {
            const float p = __expf(S[tid][s] - mnew);
            S[tid][s] = p;
            l += p;
        }
        mrun = mnew;

        #pragma unroll 2
        for (int s = 0; s < 32; s++) {
            const float p = S[tid][s];
            const float* vr = &Vt[s][0];
            #pragma unroll
            for (int d = 0; d < 64; d++) o[d] += p * vr[d];
        }
        __syncthreads();
    }

    const float inv = 1.f / l;
    const int b = bh >> 4;
    const int h = bh & (H_ - 1);
    float* yo = g_y + ((size_t)(b * T_ + row)) * C_ + h * D_;
    #pragma unroll
    for (int d = 0; d < 64; d += 4) {
        float4 t;
        t.x = o[d + 0] * inv;
        t.y = o[d + 1] * inv;
        t.z = o[d + 2] * inv;
        t.w = o[d + 3] * inv;
        *(float4*)&yo[d] = t;
    }
}

// ---------------------------------------------------------------------------
extern "C" void kernel_launch(void* const* d_in, const int* in_sizes, int n_in,
                              void* d_out, int out_size)
{
    const float* x  = (const float*)d_in[0];
    const float* Wq = (const float*)d_in[1];
    const float* bq = (const float*)d_in[2];
    const float* Wk = (const float*)d_in[3];
    const float* bk = (const float*)d_in[4];
    const float* Wv = (const float*)d_in[5];
    const float* bv = (const float*)d_in[6];
    const float* Wp = (const float*)d_in[7];
    const float* bp = (const float*)d_in[8];
    float* out = (float*)d_out;

    dim3 gq(C_ / 128, M_ / 128, 3);        // (8, 64, 3)
    qkv_gemm_kernel<<<gq, 256>>>(x, Wq, bq, Wk, bk, Wv, bv);

    dim3 gf(T_ / 128, B_ * H_);            // (16, 64)
    flash_kernel<<<gf, 128>>>();

    dim3 gp(C_ / 128, M_ / 128);           // (8, 64)
    proj_gemm_kernel<<<gp, 256>>>(Wp, bp, out);
}

// round 7
// speedup vs baseline: 3.5152x; 2.3354x over previous
#include <cuda_runtime.h>
#include <cstdint>

// Problem constants
#define B_ 4
#define T_ 2048
#define C_ 1024
#define H_ 16
#define D_ 64
#define M_ (B_ * T_)

// Scratch
__device__ float g_q[(size_t)B_ * H_ * T_ * D_];   // [B,H,T,D]
__device__ float g_k[(size_t)B_ * H_ * T_ * D_];
__device__ float g_v[(size_t)B_ * H_ * T_ * D_];
__device__ float g_y[(size_t)B_ * T_ * C_];        // [B,T,C]

// ---------------------------------------------------------------------------
// tf32 helpers
// ---------------------------------------------------------------------------
__device__ __forceinline__ uint32_t f2tf32(float f) {
    uint32_t u;
    asm("cvt.rna.tf32.f32 %0, %1;" : "=r"(u) : "f"(f));
    return u;
}

__device__ __forceinline__ float fexp2(float x) {
    float y;
    asm("ex2.approx.ftz.f32 %0, %1;" : "=f"(y) : "f"(x));
    return y;
}

__device__ __forceinline__ void mma_tf32_16x8x8(
    float* d, const uint32_t* a, const uint32_t* b, const float* c)
{
    asm volatile(
        "mma.sync.aligned.m16n8k8.row.col.f32.tf32.tf32.f32 "
        "{%0,%1,%2,%3}, {%4,%5,%6,%7}, {%8,%9}, {%10,%11,%12,%13};"
        : "=f"(d[0]), "=f"(d[1]), "=f"(d[2]), "=f"(d[3])
        : "r"(a[0]), "r"(a[1]), "r"(a[2]), "r"(a[3]),
          "r"(b[0]), "r"(b[1]),
          "f"(c[0]), "f"(c[1]), "f"(c[2]), "f"(c[3]));
}

// ---------------------------------------------------------------------------
// Tensor-core tf32 GEMM (validated in R4): out = A @ W + bias
// ---------------------------------------------------------------------------
#define AS_STRIDE 36
#define BS_STRIDE 132

__device__ __forceinline__ void gemm_body_tc(
    const float* __restrict__ A, const float* __restrict__ W,
    const float* __restrict__ bias, float* __restrict__ out, int qkv_layout)
{
    __shared__ uint32_t As[128][AS_STRIDE];
    __shared__ uint32_t Bs[32][BS_STRIDE];

    const int tid  = threadIdx.x;
    const int wid  = tid >> 5;
    const int lane = tid & 31;
    const int g    = lane >> 2;
    const int tg   = lane & 3;

    const int m0 = blockIdx.y * 128;
    const int n0 = blockIdx.x * 128;
    const int wm = (wid >> 2) * 64;
    const int wn = (wid & 3) * 32;

    float acc[4][4][4];
    #pragma unroll
    for (int i = 0; i < 4; i++)
        #pragma unroll
        for (int j = 0; j < 4; j++)
            #pragma unroll
            for (int r = 0; r < 4; r++) acc[i][j][r] = 0.f;

    float4 avr[4], bvr[4];
    #pragma unroll
    for (int i = 0; i < 4; i++) {
        const int eA = tid + i * 256;
        avr[i] = *(const float4*)(A + (size_t)(m0 + (eA >> 3)) * C_ + ((eA & 7) * 4));
        const int eB = tid + i * 256;
        bvr[i] = *(const float4*)(W + (size_t)(eB >> 5) * C_ + n0 + (eB & 31) * 4);
    }

    for (int k0 = 0; k0 < C_; k0 += 32) {
        #pragma unroll
        for (int i = 0; i < 4; i++) {
            const int eA = tid + i * 256;
            const int m  = eA >> 3;
            const int k4 = (eA & 7) * 4;
            As[m][k4 + 0] = f2tf32(avr[i].x);
            As[m][k4 + 1] = f2tf32(avr[i].y);
            As[m][k4 + 2] = f2tf32(avr[i].z);
            As[m][k4 + 3] = f2tf32(avr[i].w);
            const int eB = tid + i * 256;
            const int k  = eB >> 5;
            const int n4 = (eB & 31) * 4;
            Bs[k][n4 + 0] = f2tf32(bvr[i].x);
            Bs[k][n4 + 1] = f2tf32(bvr[i].y);
            Bs[k][n4 + 2] = f2tf32(bvr[i].z);
            Bs[k][n4 + 3] = f2tf32(bvr[i].w);
        }
        __syncthreads();

        if (k0 + 32 < C_) {
            #pragma unroll
            for (int i = 0; i < 4; i++) {
                const int eA = tid + i * 256;
                avr[i] = *(const float4*)(A + (size_t)(m0 + (eA >> 3)) * C_
                                            + k0 + 32 + ((eA & 7) * 4));
                const int eB = tid + i * 256;
                bvr[i] = *(const float4*)(W + (size_t)(k0 + 32 + (eB >> 5)) * C_
                                            + n0 + (eB & 31) * 4);
            }
        }

        #pragma unroll
        for (int ks = 0; ks < 4; ks++) {
            const int kk = ks * 8;
            uint32_t afr[4][4], bfr[4][2];
            #pragma unroll
            for (int mf = 0; mf < 4; mf++) {
                const int row = wm + mf * 16;
                afr[mf][0] = As[row + g    ][kk + tg    ];
                afr[mf][1] = As[row + g + 8][kk + tg    ];
                afr[mf][2] = As[row + g    ][kk + tg + 4];
                afr[mf][3] = As[row + g + 8][kk + tg + 4];
            }
            #pragma unroll
            for (int nf = 0; nf < 4; nf++) {
                const int col = wn + nf * 8 + g;
                bfr[nf][0] = Bs[kk + tg    ][col];
                bfr[nf][1] = Bs[kk + tg + 4][col];
            }
            #pragma unroll
            for (int mf = 0; mf < 4; mf++)
                #pragma unroll
                for (int nf = 0; nf < 4; nf++)
                    mma_tf32_16x8x8(acc[mf][nf], afr[mf], bfr[nf], acc[mf][nf]);
        }
        __syncthreads();
    }

    #pragma unroll
    for (int mf = 0; mf < 4; mf++) {
        #pragma unroll
        for (int nf = 0; nf < 4; nf++) {
            const int col = n0 + wn + nf * 8 + 2 * tg;
            const float b0 = bias[col], b1 = bias[col + 1];
            #pragma unroll
            for (int half = 0; half < 2; half++) {
                const int m = m0 + wm + mf * 16 + g + half * 8;
                const float v0 = acc[mf][nf][half * 2 + 0] + b0;
                const float v1 = acc[mf][nf][half * 2 + 1] + b1;
                const int b = m >> 11;
                const int t = m & (T_ - 1);
                if (qkv_layout) {
                    const int h = col >> 6;
                    const int d = col & (D_ - 1);
                    float2* p = (float2*)&out[(((size_t)(b * H_ + h) * T_ + t) * D_) + d];
                    *p = make_float2(v0, v1);
                } else {
                    float2* p = (float2*)&out[(size_t)m * C_ + col];
                    *p = make_float2(v0, v1);
                }
            }
        }
    }
}

__global__ __launch_bounds__(256)
void qkv_gemm_kernel(const float* __restrict__ x,
                     const float* __restrict__ Wq, const float* __restrict__ bq,
                     const float* __restrict__ Wk, const float* __restrict__ bk,
                     const float* __restrict__ Wv, const float* __restrict__ bv)
{
    const float* W; const float* bias; float* out;
    if (blockIdx.z == 0)      { W = Wq; bias = bq; out = g_q; }
    else if (blockIdx.z == 1) { W = Wk; bias = bk; out = g_k; }
    else                      { W = Wv; bias = bv; out = g_v; }
    gemm_body_tc(x, W, bias, out, 1);
}

__global__ __launch_bounds__(256)
void proj_gemm_kernel(const float* __restrict__ Wp, const float* __restrict__ bp,
                      float* __restrict__ out)
{
    gemm_body_tc(g_y, Wp, bp, out, 0);
}

// ---------------------------------------------------------------------------
// Tensor-core flash attention (tf32 mma, fp32 softmax).
// Block = 128 q rows, 4 warps; warp = 32 rows (mf=2). Key tile = 32.
// K/V tiles are 32 keys x 64 d -> row stride 68 (FIX for R5's 36 overflow).
// P staged per-warp through SMEM (32x32, stride 36) for A-operand layout.
// Scores pre-scaled by 0.125*log2(e) so softmax uses raw ex2.approx.
// ---------------------------------------------------------------------------
#define KVSTR_ 68   // 64 d + 4 pad; %32==4 -> QK B-frag reads conflict-free
#define PSTR_  36   // 32 keys + 4 pad

__global__ __launch_bounds__(128)
void flash_tc_kernel()
{
    __shared__ uint32_t Kt[32][KVSTR_];
    __shared__ uint32_t Vt[32][KVSTR_];
    __shared__ uint32_t Sp[4][32][PSTR_];

    const int bh   = blockIdx.y;
    const int qi   = blockIdx.x;
    const int tid  = threadIdx.x;
    const int w    = tid >> 5;
    const int lane = tid & 31;
    const int g    = lane >> 2;
    const int tg   = lane & 3;
    const int Q0   = qi * 128;
    const int wrow = Q0 + w * 32;

    const float* Qb = g_q + (size_t)bh * T_ * D_;
    const float* Kb = g_k + (size_t)bh * T_ * D_;
    const float* Vb = g_v + (size_t)bh * T_ * D_;

    // Q fragments in registers, pre-scaled by 1/sqrt(D) * log2(e)
    const float qscale = 0.125f * 1.4426950408889634f;
    uint32_t qa[2][8][4];
    #pragma unroll
    for (int mf = 0; mf < 2; mf++) {
        const int r0 = wrow + mf * 16 + g;
        const int r1 = r0 + 8;
        #pragma unroll
        for (int ks = 0; ks < 8; ks++) {
            qa[mf][ks][0] = f2tf32(Qb[(size_t)r0 * D_ + ks * 8 + tg    ] * qscale);
            qa[mf][ks][1] = f2tf32(Qb[(size_t)r1 * D_ + ks * 8 + tg    ] * qscale);
            qa[mf][ks][2] = f2tf32(Qb[(size_t)r0 * D_ + ks * 8 + tg + 4] * qscale);
            qa[mf][ks][3] = f2tf32(Qb[(size_t)r1 * D_ + ks * 8 + tg + 4] * qscale);
        }
    }

    float onf[2][8][4];
    #pragma unroll
    for (int mf = 0; mf < 2; mf++)
        #pragma unroll
        for (int nf = 0; nf < 8; nf++)
            #pragma unroll
            for (int c = 0; c < 4; c++) onf[mf][nf][c] = 0.f;
    float mrow[2][2] = {{-1e30f, -1e30f}, {-1e30f, -1e30f}};
    float lrow[2][2] = {{0.f, 0.f}, {0.f, 0.f}};

    const int ntile   = 4 * (qi + 1);
    const int maskBeg = 4 * qi;    // tiles >= this need causal masking

    for (int jt = 0; jt < ntile; jt++) {
        const int base = jt * 32;

        // cooperative K/V tile load (32 keys x 64 d), convert to tf32
        #pragma unroll
        for (int i = 0; i < 4; i++) {
            const int e   = tid + i * 128;       // 0..511
            const int key = e >> 4;
            const int c   = (e & 15) * 4;
            float4 kv = *(const float4*)&Kb[(size_t)(base + key) * D_ + c];
            float4 vv = *(const float4*)&Vb[(size_t)(base + key) * D_ + c];
            Kt[key][c + 0] = f2tf32(kv.x);
            Kt[key][c + 1] = f2tf32(kv.y);
            Kt[key][c + 2] = f2tf32(kv.z);
            Kt[key][c + 3] = f2tf32(kv.w);
            Vt[key][c + 0] = f2tf32(vv.x);
            Vt[key][c + 1] = f2tf32(vv.y);
            Vt[key][c + 2] = f2tf32(vv.z);
            Vt[key][c + 3] = f2tf32(vv.w);
        }
        __syncthreads();

        // --- QK^T: s[mf][nf] = Q_warp @ K_tile^T (scaled, base-2) ---
        float s[2][4][4];
        #pragma unroll
        for (int mf = 0; mf < 2; mf++)
            #pragma unroll
            for (int nf = 0; nf < 4; nf++)
                #pragma unroll
                for (int c = 0; c < 4; c++) s[mf][nf][c] = 0.f;

        #pragma unroll
        for (int nf = 0; nf < 4; nf++) {
            #pragma unroll
            for (int ks = 0; ks < 8; ks++) {
                uint32_t b[2];
                b[0] = Kt[nf * 8 + g][ks * 8 + tg    ];
                b[1] = Kt[nf * 8 + g][ks * 8 + tg + 4];
                mma_tf32_16x8x8(s[0][nf], qa[0][ks], b, s[0][nf]);
                mma_tf32_16x8x8(s[1][nf], qa[1][ks], b, s[1][nf]);
            }
        }

        // causal mask on diagonal tiles
        if (jt >= maskBeg) {
            #pragma unroll
            for (int mf = 0; mf < 2; mf++)
                #pragma unroll
                for (int nf = 0; nf < 4; nf++)
                    #pragma unroll
                    for (int c = 0; c < 4; c++) {
                        const int row = wrow + mf * 16 + g + (c >> 1) * 8;
                        const int col = base + nf * 8 + 2 * tg + (c & 1);
                        if (col > row) s[mf][nf][c] = -1e30f;
                    }
        }

        // --- online softmax (base-2) per row (4 rows/thread) ---
        #pragma unroll
        for (int mf = 0; mf < 2; mf++) {
            #pragma unroll
            for (int h = 0; h < 2; h++) {
                float rmax = -1e30f;
                #pragma unroll
                for (int nf = 0; nf < 4; nf++)
                    rmax = fmaxf(rmax, fmaxf(s[mf][nf][h * 2], s[mf][nf][h * 2 + 1]));
                rmax = fmaxf(rmax, __shfl_xor_sync(0xffffffffu, rmax, 1));
                rmax = fmaxf(rmax, __shfl_xor_sync(0xffffffffu, rmax, 2));

                const float mnew = fmaxf(mrow[mf][h], rmax);
                const float corr = fexp2(mrow[mf][h] - mnew);
                mrow[mf][h] = mnew;

                float rsum = 0.f;
                #pragma unroll
                for (int nf = 0; nf < 4; nf++) {
                    float p0 = fexp2(s[mf][nf][h * 2    ] - mnew);
                    float p1 = fexp2(s[mf][nf][h * 2 + 1] - mnew);
                    s[mf][nf][h * 2    ] = p0;
                    s[mf][nf][h * 2 + 1] = p1;
                    rsum += p0 + p1;
                }
                rsum += __shfl_xor_sync(0xffffffffu, rsum, 1);
                rsum += __shfl_xor_sync(0xffffffffu, rsum, 2);
                lrow[mf][h] = lrow[mf][h] * corr + rsum;

                #pragma unroll
                for (int nf = 0; nf < 8; nf++) {
                    onf[mf][nf][h * 2    ] *= corr;
                    onf[mf][nf][h * 2 + 1] *= corr;
                }
            }
        }

        // --- stage P (tf32) into per-warp SMEM for A-operand layout ---
        __syncwarp();
        #pragma unroll
        for (int mf = 0; mf < 2; mf++)
            #pragma unroll
            for (int nf = 0; nf < 4; nf++) {
                Sp[w][mf * 16 + g    ][nf * 8 + 2 * tg    ] = f2tf32(s[mf][nf][0]);
                Sp[w][mf * 16 + g    ][nf * 8 + 2 * tg + 1] = f2tf32(s[mf][nf][1]);
                Sp[w][mf * 16 + g + 8][nf * 8 + 2 * tg    ] = f2tf32(s[mf][nf][2]);
                Sp[w][mf * 16 + g + 8][nf * 8 + 2 * tg + 1] = f2tf32(s[mf][nf][3]);
            }
        __syncwarp();

        // --- P @ V accumulate into onf ---
        #pragma unroll
        for (int pk = 0; pk < 4; pk++) {
            uint32_t a0[4], a1[4];
            a0[0] = Sp[w][g     ][pk * 8 + tg    ];
            a0[1] = Sp[w][g + 8 ][pk * 8 + tg    ];
            a0[2] = Sp[w][g     ][pk * 8 + tg + 4];
            a0[3] = Sp[w][g + 8 ][pk * 8 + tg + 4];
            a1[0] = Sp[w][g + 16][pk * 8 + tg    ];
            a1[1] = Sp[w][g + 24][pk * 8 + tg    ];
            a1[2] = Sp[w][g + 16][pk * 8 + tg + 4];
            a1[3] = Sp[w][g + 24][pk * 8 + tg + 4];
            #pragma unroll
            for (int nf = 0; nf < 8; nf++) {
                uint32_t b[2];
                b[0] = Vt[pk * 8 + tg    ][nf * 8 + g];
                b[1] = Vt[pk * 8 + tg + 4][nf * 8 + g];
                mma_tf32_16x8x8(onf[0][nf], a0, b, onf[0][nf]);
                mma_tf32_16x8x8(onf[1][nf], a1, b, onf[1][nf]);
            }
        }
        __syncthreads();   // before next tile overwrites Kt/Vt
    }

    // --- normalize and write out ---
    const int b  = bh >> 4;
    const int hh = bh & (H_ - 1);
    #pragma unroll
    for (int mf = 0; mf < 2; mf++) {
        const float inv0 = 1.f / lrow[mf][0];
        const float inv1 = 1.f / lrow[mf][1];
        const int r0 = wrow + mf * 16 + g;
        #pragma unroll
        for (int nf = 0; nf < 8; nf++) {
            const int d = nf * 8 + 2 * tg;
            float2* p0 = (float2*)&g_y[((size_t)(b * T_ + r0) * C_) + hh * D_ + d];
            *p0 = make_float2(onf[mf][nf][0] * inv0, onf[mf][nf][1] * inv0);
            float2* p1 = (float2*)&g_y[((size_t)(b * T_ + r0 + 8) * C_) + hh * D_ + d];
            *p1 = make_float2(onf[mf][nf][2] * inv1, onf[mf][nf][3] * inv1);
        }
    }
}

// ---------------------------------------------------------------------------
extern "C" void kernel_launch(void* const* d_in, const int* in_sizes, int n_in,
                              void* d_out, int out_size)
{
    const float* x  = (const float*)d_in[0];
    const float* Wq = (const float*)d_in[1];
    const float* bq = (const float*)d_in[2];
    const float* Wk = (const float*)d_in[3];
    const float* bk = (const float*)d_in[4];
    const float* Wv = (const float*)d_in[5];
    const float* bv = (const float*)d_in[6];
    const float* Wp = (const float*)d_in[7];
    const float* bp = (const float*)d_in[8];
    float* out = (float*)d_out;

    dim3 gq(C_ / 128, M_ / 128, 3);
    qkv_gemm_kernel<<<gq, 256>>>(x, Wq, bq, Wk, bk, Wv, bv);

    dim3 gf(T_ / 128, B_ * H_);
    flash_tc_kernel<<<gf, 128>>>();

    dim3 gp(C_ / 128, M_ / 128);
    proj_gemm_kernel<<<gp, 256>>>(Wp, bp, out);
}

// round 11
// speedup vs baseline: 4.0544x; 1.1534x over previous
#include <cuda_runtime.h>
#include <cstdint>

// Problem constants
#define B_ 4
#define T_ 2048
#define C_ 1024
#define H_ 16
#define D_ 64
#define M_ (B_ * T_)

// Scratch: tf32-bit tensors (uint32) unless noted
__device__ uint32_t g_q[(size_t)B_ * H_ * T_ * D_];   // tf32 bits, q pre-scaled
__device__ uint32_t g_k[(size_t)B_ * H_ * T_ * D_];
__device__ uint32_t g_v[(size_t)B_ * H_ * T_ * D_];
__device__ uint32_t g_yt[(size_t)B_ * T_ * C_];       // attention out, tf32 bits
__device__ uint32_t g_xt[(size_t)M_ * C_];            // x, tf32 bits
__device__ uint32_t g_wt[4][(size_t)C_ * C_];         // W (k-major [k][n]), tf32 bits

// ---------------------------------------------------------------------------
// helpers
// ---------------------------------------------------------------------------
__device__ __forceinline__ uint32_t f2tf32(float f) {
    uint32_t u;
    asm("cvt.rna.tf32.f32 %0, %1;" : "=r"(u) : "f"(f));
    return u;
}
__device__ __forceinline__ float fexp2(float x) {
    float y;
    asm("ex2.approx.ftz.f32 %0, %1;" : "=f"(y) : "f"(x));
    return y;
}
__device__ __forceinline__ void mma_tf32_16x8x8(
    float* d, const uint32_t* a, const uint32_t* b, const float* c)
{
    asm volatile(
        "mma.sync.aligned.m16n8k8.row.col.f32.tf32.tf32.f32 "
        "{%0,%1,%2,%3}, {%4,%5,%6,%7}, {%8,%9}, {%10,%11,%12,%13};"
        : "=f"(d[0]), "=f"(d[1]), "=f"(d[2]), "=f"(d[3])
        : "r"(a[0]), "r"(a[1]), "r"(a[2]), "r"(a[3]),
          "r"(b[0]), "r"(b[1]),
          "f"(c[0]), "f"(c[1]), "f"(c[2]), "f"(c[3]));
}
__device__ __forceinline__ uint32_t smem_u32(const void* p) {
    uint32_t a;
    asm("{ .reg .u64 t; cvta.to.shared.u64 t, %1; cvt.u32.u64 %0, t; }"
        : "=r"(a) : "l"(p));
    return a;
}
__device__ __forceinline__ void cp_async16(uint32_t dst_smem, const void* src) {
    asm volatile("cp.async.cg.shared.global [%0], [%1], 16;"
                 :: "r"(dst_smem), "l"(src) : "memory");
}
#define CP_COMMIT()  asm volatile("cp.async.commit_group;" ::: "memory")
#define CP_WAIT(n)   asm volatile("cp.async.wait_group %0;" :: "n"(n) : "memory")

// ---------------------------------------------------------------------------
// fp32 -> tf32-bits conversions (reference __device__ symbols directly;
// no host-side cudaGetSymbolAddress needed)
// ---------------------------------------------------------------------------
__global__ __launch_bounds__(256)
void cvt_w_kernel(const float4* __restrict__ Wq, const float4* __restrict__ Wk,
                  const float4* __restrict__ Wv, const float4* __restrict__ Wp)
{
    const float4* src = (blockIdx.z == 0) ? Wq : (blockIdx.z == 1) ? Wk
                      : (blockIdx.z == 2) ? Wv : Wp;
    uint4* dst = (uint4*)g_wt[blockIdx.z];
    const int i = blockIdx.x * blockDim.x + threadIdx.x;   // < C_*C_/4
    float4 v = src[i];
    uint4 u;
    u.x = f2tf32(v.x); u.y = f2tf32(v.y);
    u.z = f2tf32(v.z); u.w = f2tf32(v.w);
    dst[i] = u;
}

__global__ __launch_bounds__(256)
void cvt_x_kernel(const float4* __restrict__ x)
{
    uint4* dst = (uint4*)g_xt;
    const int i = blockIdx.x * blockDim.x + threadIdx.x;   // < M_*C_/4
    float4 v = x[i];
    uint4 u;
    u.x = f2tf32(v.x); u.y = f2tf32(v.y);
    u.z = f2tf32(v.z); u.w = f2tf32(v.w);
    dst[i] = u;
}

// ---------------------------------------------------------------------------
// tf32 tensor-core GEMM, cp.async ping-pong, 64x64 warp tiles.
// C[m][n] = At[m][k] @ Bt[k][n]; At/Bt are tf32 bits in GMEM.
// CTA: 128 threads = 4 warps (2m x 2n), tile 128x128, K-chunk 32.
// mode 0: out fp32 = acc + bias (row-major [M,C])
// mode 1: out tf32-bits = cvt((acc + bias) * scale), scattered to [B,H,T,D]
// ---------------------------------------------------------------------------
#define ASTR 36
#define BSTR 132
#define AS_WORDS (128 * ASTR)          // 4608
#define BS_WORDS (32 * BSTR)           // 4224
#define STG_WORDS (AS_WORDS + BS_WORDS)
#define GSMEM_BYTES (2 * STG_WORDS * 4)   // 70656

__device__ __forceinline__ void gemm_stage(
    uint32_t sbase, int p, const uint32_t* __restrict__ At,
    const uint32_t* __restrict__ Bt, int m0, int n0, int k0, int tid)
{
    const uint32_t as = sbase + (uint32_t)p * STG_WORDS * 4;
    const uint32_t bs = as + AS_WORDS * 4;
    #pragma unroll
    for (int i = 0; i < 8; i++) {
        const int idx = tid + i * 128;               // 0..1023
        const int row = idx >> 3;                    // 0..127
        const int cg  = idx & 7;                     // k-subgroup (x4)
        cp_async16(as + (uint32_t)(row * ASTR + cg * 4) * 4,
                   At + (size_t)(m0 + row) * C_ + k0 + cg * 4);
        const int k  = idx >> 5;                     // 0..31
        const int n4 = (idx & 31) * 4;               // 0..124
        cp_async16(bs + (uint32_t)(k * BSTR + n4) * 4,
                   Bt + (size_t)(k0 + k) * C_ + n0 + n4);
    }
    CP_COMMIT();
}

__device__ __forceinline__ void gemm_body(
    const uint32_t* __restrict__ At, const uint32_t* __restrict__ Bt,
    const float* __restrict__ bias, void* __restrict__ out,
    int mode, float scale)
{
    extern __shared__ uint32_t smem[];
    const uint32_t sbase = smem_u32(smem);
    const int tid  = threadIdx.x;        // 0..127
    const int w    = tid >> 5;           // 0..3
    const int lane = tid & 31;
    const int g    = lane >> 2;
    const int tg   = lane & 3;
    const int m0   = blockIdx.y * 128;
    const int n0   = blockIdx.x * 128;
    const int wm   = (w & 1) * 64;
    const int wn   = (w >> 1) * 64;

    float acc[4][8][4];
    #pragma unroll
    for (int i = 0; i < 4; i++)
        #pragma unroll
        for (int j = 0; j < 8; j++)
            #pragma unroll
            for (int r = 0; r < 4; r++) acc[i][j][r] = 0.f;

    gemm_stage(sbase, 0, At, Bt, m0, n0, 0, tid);

    #define NCHUNK 32
    for (int c = 0; c < NCHUNK; c++) {
        const int p = c & 1;
        if (c + 1 < NCHUNK)
            gemm_stage(sbase, p ^ 1, At, Bt, m0, n0, (c + 1) * 32, tid);
        if (c + 1 < NCHUNK) CP_WAIT(1); else CP_WAIT(0);
        __syncthreads();

        const uint32_t* As = smem + (size_t)p * STG_WORDS;
        const uint32_t* Bs = As + AS_WORDS;
        #pragma unroll
        for (int ks = 0; ks < 4; ks++) {
            const int kk = ks * 8;
            uint32_t afr[4][4], bfr[8][2];
            #pragma unroll
            for (int mf = 0; mf < 4; mf++) {
                const int row = wm + mf * 16;
                afr[mf][0] = As[(row + g    ) * ASTR + kk + tg    ];
                afr[mf][1] = As[(row + g + 8) * ASTR + kk + tg    ];
                afr[mf][2] = As[(row + g    ) * ASTR + kk + tg + 4];
                afr[mf][3] = As[(row + g + 8) * ASTR + kk + tg + 4];
            }
            #pragma unroll
            for (int nf = 0; nf < 8; nf++) {
                const int col = wn + nf * 8 + g;
                bfr[nf][0] = Bs[(kk + tg    ) * BSTR + col];
                bfr[nf][1] = Bs[(kk + tg + 4) * BSTR + col];
            }
            #pragma unroll
            for (int mf = 0; mf < 4; mf++)
                #pragma unroll
                for (int nf = 0; nf < 8; nf++)
                    mma_tf32_16x8x8(acc[mf][nf], afr[mf], bfr[nf], acc[mf][nf]);
        }
        __syncthreads();
    }

    // epilogue
    #pragma unroll
    for (int mf = 0; mf < 4; mf++) {
        #pragma unroll
        for (int nf = 0; nf < 8; nf++) {
            const int col = n0 + wn + nf * 8 + 2 * tg;
            const float b0 = bias[col], b1 = bias[col + 1];
            #pragma unroll
            for (int half = 0; half < 2; half++) {
                const int m = m0 + wm + mf * 16 + g + half * 8;
                const float v0 = acc[mf][nf][half * 2 + 0] + b0;
                const float v1 = acc[mf][nf][half * 2 + 1] + b1;
                if (mode == 0) {
                    float2* p2 = (float2*)((float*)out + (size_t)m * C_ + col);
                    *p2 = make_float2(v0, v1);
                } else {
                    const int bb = m >> 11;
                    const int t  = m & (T_ - 1);
                    const int h  = col >> 6;
                    const int d  = col & (D_ - 1);
                    uint32_t* p2 = (uint32_t*)out
                        + (((size_t)(bb * H_ + h) * T_ + t) * D_) + d;
                    p2[0] = f2tf32(v0 * scale);
                    p2[1] = f2tf32(v1 * scale);
                }
            }
        }
    }
}

#define QSCALE_ (0.125f * 1.4426950408889634f)

__global__ __launch_bounds__(128)
void qkv_gemm_kernel(const float* __restrict__ bq, const float* __restrict__ bk,
                     const float* __restrict__ bv)
{
    const float* bias; uint32_t* out; float scale;
    if (blockIdx.z == 0)      { bias = bq; out = g_q; scale = QSCALE_; }
    else if (blockIdx.z == 1) { bias = bk; out = g_k; scale = 1.f; }
    else                      { bias = bv; out = g_v; scale = 1.f; }
    gemm_body(g_xt, g_wt[blockIdx.z], bias, out, 1, scale);
}

__global__ __launch_bounds__(128)
void proj_gemm_kernel(const float* __restrict__ bp, float* __restrict__ out)
{
    gemm_body(g_yt, g_wt[3], bp, out, 0, 1.f);
}

// ---------------------------------------------------------------------------
// Tensor-core flash attention (tf32 mma, fp32 softmax). R7 structure;
// q/k/v already tf32 bits (q pre-scaled); K/V staged via cp.async;
// output written as tf32 bits to g_yt.
// ---------------------------------------------------------------------------
#define KVSTR_ 68
#define PSTR_  36

__global__ __launch_bounds__(128)
void flash_tc_kernel()
{
    __shared__ uint32_t Kt[32][KVSTR_];
    __shared__ uint32_t Vt[32][KVSTR_];
    __shared__ uint32_t Sp[4][32][PSTR_];

    const int bh   = blockIdx.y;
    const int qi   = blockIdx.x;
    const int tid  = threadIdx.x;
    const int w    = tid >> 5;
    const int lane = tid & 31;
    const int g    = lane >> 2;
    const int tg   = lane & 3;
    const int wrow = qi * 128 + w * 32;

    const uint32_t* Qb = g_q + (size_t)bh * T_ * D_;
    const uint32_t* Kb = g_k + (size_t)bh * T_ * D_;
    const uint32_t* Vb = g_v + (size_t)bh * T_ * D_;
    const uint32_t kbase = smem_u32(&Kt[0][0]);
    const uint32_t vbase = smem_u32(&Vt[0][0]);

    // Q fragments (already tf32 bits, already scaled)
    uint32_t qa[2][8][4];
    #pragma unroll
    for (int mf = 0; mf < 2; mf++) {
        const int r0 = wrow + mf * 16 + g;
        const int r1 = r0 + 8;
        #pragma unroll
        for (int ks = 0; ks < 8; ks++) {
            qa[mf][ks][0] = Qb[(size_t)r0 * D_ + ks * 8 + tg    ];
            qa[mf][ks][1] = Qb[(size_t)r1 * D_ + ks * 8 + tg    ];
            qa[mf][ks][2] = Qb[(size_t)r0 * D_ + ks * 8 + tg + 4];
            qa[mf][ks][3] = Qb[(size_t)r1 * D_ + ks * 8 + tg + 4];
        }
    }

    float onf[2][8][4];
    #pragma unroll
    for (int mf = 0; mf < 2; mf++)
        #pragma unroll
        for (int nf = 0; nf < 8; nf++)
            #pragma unroll
            for (int c = 0; c < 4; c++) onf[mf][nf][c] = 0.f;
    float mrow[2][2] = {{-1e30f, -1e30f}, {-1e30f, -1e30f}};
    float lrow[2][2] = {{0.f, 0.f}, {0.f, 0.f}};

    const int ntile   = 4 * (qi + 1);
    const int maskBeg = 4 * qi;

    for (int jt = 0; jt < ntile; jt++) {
        const int base = jt * 32;

        // cp.async K/V tile staging (32 keys x 64 d)
        #pragma unroll
        for (int i = 0; i < 4; i++) {
            const int e   = tid + i * 128;
            const int key = e >> 4;
            const int c   = (e & 15) * 4;
            cp_async16(kbase + (uint32_t)(key * KVSTR_ + c) * 4,
                       Kb + (size_t)(base + key) * D_ + c);
            cp_async16(vbase + (uint32_t)(key * KVSTR_ + c) * 4,
                       Vb + (size_t)(base + key) * D_ + c);
        }
        CP_COMMIT();
        CP_WAIT(0);
        __syncthreads();

        // QK^T
        float s[2][4][4];
        #pragma unroll
        for (int mf = 0; mf < 2; mf++)
            #pragma unroll
            for (int nf = 0; nf < 4; nf++)
                #pragma unroll
                for (int c = 0; c < 4; c++) s[mf][nf][c] = 0.f;

        #pragma unroll
        for (int nf = 0; nf < 4; nf++) {
            #pragma unroll
            for (int ks = 0; ks < 8; ks++) {
                uint32_t b[2];
                b[0] = Kt[nf * 8 + g][ks * 8 + tg    ];
                b[1] = Kt[nf * 8 + g][ks * 8 + tg + 4];
                mma_tf32_16x8x8(s[0][nf], qa[0][ks], b, s[0][nf]);
                mma_tf32_16x8x8(s[1][nf], qa[1][ks], b, s[1][nf]);
            }
        }

        if (jt >= maskBeg) {
            #pragma unroll
            for (int mf = 0; mf < 2; mf++)
                #pragma unroll
                for (int nf = 0; nf < 4; nf++)
                    #pragma unroll
                    for (int c = 0; c < 4; c++) {
                        const int row = wrow + mf * 16 + g + (c >> 1) * 8;
                        const int col = base + nf * 8 + 2 * tg + (c & 1);
                        if (col > row) s[mf][nf][c] = -1e30f;
                    }
        }

        // online softmax (base-2)
        #pragma unroll
        for (int mf = 0; mf < 2; mf++) {
            #pragma unroll
            for (int h = 0; h < 2; h++) {
                float rmax = -1e30f;
                #pragma unroll
                for (int nf = 0; nf < 4; nf++)
                    rmax = fmaxf(rmax, fmaxf(s[mf][nf][h * 2], s[mf][nf][h * 2 + 1]));
                rmax = fmaxf(rmax, __shfl_xor_sync(0xffffffffu, rmax, 1));
                rmax = fmaxf(rmax, __shfl_xor_sync(0xffffffffu, rmax, 2));

                const float mnew = fmaxf(mrow[mf][h], rmax);
                const float corr = fexp2(mrow[mf][h] - mnew);
                mrow[mf][h] = mnew;

                float rsum = 0.f;
                #pragma unroll
                for (int nf = 0; nf < 4; nf++) {
                    float p0 = fexp2(s[mf][nf][h * 2    ] - mnew);
                    float p1 = fexp2(s[mf][nf][h * 2 + 1] - mnew);
                    s[mf][nf][h * 2    ] = p0;
                    s[mf][nf][h * 2 + 1] = p1;
                    rsum += p0 + p1;
                }
                rsum += __shfl_xor_sync(0xffffffffu, rsum, 1);
                rsum += __shfl_xor_sync(0xffffffffu, rsum, 2);
                lrow[mf][h] = lrow[mf][h] * corr + rsum;

                #pragma unroll
                for (int nf = 0; nf < 8; nf++) {
                    onf[mf][nf][h * 2    ] *= corr;
                    onf[mf][nf][h * 2 + 1] *= corr;
                }
            }
        }

        // stage P (tf32 bits) for A-operand layout
        __syncwarp();
        #pragma unroll
        for (int mf = 0; mf < 2; mf++)
            #pragma unroll
            for (int nf = 0; nf < 4; nf++) {
                Sp[w][mf * 16 + g    ][nf * 8 + 2 * tg    ] = f2tf32(s[mf][nf][0]);
                Sp[w][mf * 16 + g    ][nf * 8 + 2 * tg + 1] = f2tf32(s[mf][nf][1]);
                Sp[w][mf * 16 + g + 8][nf * 8 + 2 * tg    ] = f2tf32(s[mf][nf][2]);
                Sp[w][mf * 16 + g + 8][nf * 8 + 2 * tg + 1] = f2tf32(s[mf][nf][3]);
            }
        __syncwarp();

        // P @ V
        #pragma unroll
        for (int pk = 0; pk < 4; pk++) {
            uint32_t a0[4], a1[4];
            a0[0] = Sp[w][g     ][pk * 8 + tg    ];
            a0[1] = Sp[w][g + 8 ][pk * 8 + tg    ];
            a0[2] = Sp[w][g     ][pk * 8 + tg + 4];
            a0[3] = Sp[w][g + 8 ][pk * 8 + tg + 4];
            a1[0] = Sp[w][g + 16][pk * 8 + tg    ];
            a1[1] = Sp[w][g + 24][pk * 8 + tg    ];
            a1[2] = Sp[w][g + 16][pk * 8 + tg + 4];
            a1[3] = Sp[w][g + 24][pk * 8 + tg + 4];
            #pragma unroll
            for (int nf = 0; nf < 8; nf++) {
                uint32_t b[2];
                b[0] = Vt[pk * 8 + tg    ][nf * 8 + g];
                b[1] = Vt[pk * 8 + tg + 4][nf * 8 + g];
                mma_tf32_16x8x8(onf[0][nf], a0, b, onf[0][nf]);
                mma_tf32_16x8x8(onf[1][nf], a1, b, onf[1][nf]);
            }
        }
        __syncthreads();
    }

    // normalize, convert to tf32 bits, write to g_yt
    const int b  = bh >> 4;
    const int hh = bh & (H_ - 1);
    #pragma unroll
    for (int mf = 0; mf < 2; mf++) {
        const float inv0 = 1.f / lrow[mf][0];
        const float inv1 = 1.f / lrow[mf][1];
        const int r0 = wrow + mf * 16 + g;
        #pragma unroll
        for (int nf = 0; nf < 8; nf++) {
            const int d = nf * 8 + 2 * tg;
            uint32_t* p0 = &g_yt[((size_t)(b * T_ + r0) * C_) + hh * D_ + d];
            p0[0] = f2tf32(onf[mf][nf][0] * inv0);
            p0[1] = f2tf32(onf[mf][nf][1] * inv0);
            uint32_t* p1 = &g_yt[((size_t)(b * T_ + r0 + 8) * C_) + hh * D_ + d];
            p1[0] = f2tf32(onf[mf][nf][2] * inv1);
            p1[1] = f2tf32(onf[mf][nf][3] * inv1);
        }
    }
}

// ---------------------------------------------------------------------------
extern "C" void kernel_launch(void* const* d_in, const int* in_sizes, int n_in,
                              void* d_out, int out_size)
{
    const float* x  = (const float*)d_in[0];
    const float* Wq = (const float*)d_in[1];
    const float* bq = (const float*)d_in[2];
    const float* Wk = (const float*)d_in[3];
    const float* bk = (const float*)d_in[4];
    const float* Wv = (const float*)d_in[5];
    const float* bv = (const float*)d_in[6];
    const float* Wp = (const float*)d_in[7];
    const float* bp = (const float*)d_in[8];
    float* out = (float*)d_out;

    cudaFuncSetAttribute(qkv_gemm_kernel,
                         cudaFuncAttributeMaxDynamicSharedMemorySize, GSMEM_BYTES);
    cudaFuncSetAttribute(proj_gemm_kernel,
                         cudaFuncAttributeMaxDynamicSharedMemorySize, GSMEM_BYTES);

    const int wn4 = (C_ * C_) / 4;                  // 262144
    dim3 gw(wn4 / 256, 1, 4);
    cvt_w_kernel<<<gw, 256>>>((const float4*)Wq, (const float4*)Wk,
                              (const float4*)Wv, (const float4*)Wp);
    const int xn4 = (M_ * C_) / 4;                  // 2097152
    cvt_x_kernel<<<xn4 / 256, 256>>>((const float4*)x);

    dim3 gq(C_ / 128, M_ / 128, 3);
    qkv_gemm_kernel<<<gq, 128, GSMEM_BYTES>>>(bq, bk, bv);

    dim3 gf(T_ / 128, B_ * H_);
    flash_tc_kernel<<<gf, 128>>>();

    dim3 gp(C_ / 128, M_ / 128);
    proj_gemm_kernel<<<gp, 128, GSMEM_BYTES>>>(bp, out);
}

// round 12
// speedup vs baseline: 4.1143x; 1.0148x over previous
#include <cuda_runtime.h>
#include <cstdint>

// Problem constants
#define B_ 4
#define T_ 2048
#define C_ 1024
#define H_ 16
#define D_ 64
#define M_ (B_ * T_)

// Scratch: tf32-bit tensors (uint32) unless noted
__device__ uint32_t g_q[(size_t)B_ * H_ * T_ * D_];   // tf32 bits, q pre-scaled
__device__ uint32_t g_k[(size_t)B_ * H_ * T_ * D_];
__device__ uint32_t g_v[(size_t)B_ * H_ * T_ * D_];
__device__ uint32_t g_yt[(size_t)B_ * T_ * C_];       // attention out, tf32 bits
__device__ uint32_t g_xt[(size_t)M_ * C_];            // x, tf32 bits
__device__ uint32_t g_wt[4][(size_t)C_ * C_];         // W (k-major [k][n]), tf32 bits

// ---------------------------------------------------------------------------
// helpers
// ---------------------------------------------------------------------------
__device__ __forceinline__ uint32_t f2tf32(float f) {
    uint32_t u;
    asm("cvt.rna.tf32.f32 %0, %1;" : "=r"(u) : "f"(f));
    return u;
}
__device__ __forceinline__ float fexp2(float x) {
    float y;
    asm("ex2.approx.ftz.f32 %0, %1;" : "=f"(y) : "f"(x));
    return y;
}
__device__ __forceinline__ void mma_tf32_16x8x8(
    float* d, const uint32_t* a, const uint32_t* b, const float* c)
{
    asm volatile(
        "mma.sync.aligned.m16n8k8.row.col.f32.tf32.tf32.f32 "
        "{%0,%1,%2,%3}, {%4,%5,%6,%7}, {%8,%9}, {%10,%11,%12,%13};"
        : "=f"(d[0]), "=f"(d[1]), "=f"(d[2]), "=f"(d[3])
        : "r"(a[0]), "r"(a[1]), "r"(a[2]), "r"(a[3]),
          "r"(b[0]), "r"(b[1]),
          "f"(c[0]), "f"(c[1]), "f"(c[2]), "f"(c[3]));
}
__device__ __forceinline__ uint32_t smem_u32(const void* p) {
    uint32_t a;
    asm("{ .reg .u64 t; cvta.to.shared.u64 t, %1; cvt.u32.u64 %0, t; }"
        : "=r"(a) : "l"(p));
    return a;
}
__device__ __forceinline__ void cp_async16(uint32_t dst_smem, const void* src) {
    asm volatile("cp.async.cg.shared.global [%0], [%1], 16;"
                 :: "r"(dst_smem), "l"(src) : "memory");
}
#define CP_COMMIT()  asm volatile("cp.async.commit_group;" ::: "memory")
#define CP_WAIT(n)   asm volatile("cp.async.wait_group %0;" :: "n"(n) : "memory")

// ---------------------------------------------------------------------------
// fp32 -> tf32-bits conversions
// ---------------------------------------------------------------------------
__global__ __launch_bounds__(256)
void cvt_w_kernel(const float4* __restrict__ Wq, const float4* __restrict__ Wk,
                  const float4* __restrict__ Wv, const float4* __restrict__ Wp)
{
    const float4* src = (blockIdx.z == 0) ? Wq : (blockIdx.z == 1) ? Wk
                      : (blockIdx.z == 2) ? Wv : Wp;
    uint4* dst = (uint4*)g_wt[blockIdx.z];
    const int i = blockIdx.x * blockDim.x + threadIdx.x;
    float4 v = src[i];
    uint4 u;
    u.x = f2tf32(v.x); u.y = f2tf32(v.y);
    u.z = f2tf32(v.z); u.w = f2tf32(v.w);
    dst[i] = u;
}

__global__ __launch_bounds__(256)
void cvt_x_kernel(const float4* __restrict__ x)
{
    uint4* dst = (uint4*)g_xt;
    const int i = blockIdx.x * blockDim.x + threadIdx.x;
    float4 v = x[i];
    uint4 u;
    u.x = f2tf32(v.x); u.y = f2tf32(v.y);
    u.z = f2tf32(v.z); u.w = f2tf32(v.w);
    dst[i] = u;
}

// ---------------------------------------------------------------------------
// tf32 tensor-core GEMM (unchanged from R11)
// ---------------------------------------------------------------------------
#define ASTR 36
#define BSTR 132
#define AS_WORDS (128 * ASTR)
#define BS_WORDS (32 * BSTR)
#define STG_WORDS (AS_WORDS + BS_WORDS)
#define GSMEM_BYTES (2 * STG_WORDS * 4)

__device__ __forceinline__ void gemm_stage(
    uint32_t sbase, int p, const uint32_t* __restrict__ At,
    const uint32_t* __restrict__ Bt, int m0, int n0, int k0, int tid)
{
    const uint32_t as = sbase + (uint32_t)p * STG_WORDS * 4;
    const uint32_t bs = as + AS_WORDS * 4;
    #pragma unroll
    for (int i = 0; i < 8; i++) {
        const int idx = tid + i * 128;
        const int row = idx >> 3;
        const int cg  = idx & 7;
        cp_async16(as + (uint32_t)(row * ASTR + cg * 4) * 4,
                   At + (size_t)(m0 + row) * C_ + k0 + cg * 4);
        const int k  = idx >> 5;
        const int n4 = (idx & 31) * 4;
        cp_async16(bs + (uint32_t)(k * BSTR + n4) * 4,
                   Bt + (size_t)(k0 + k) * C_ + n0 + n4);
    }
    CP_COMMIT();
}

__device__ __forceinline__ void gemm_body(
    const uint32_t* __restrict__ At, const uint32_t* __restrict__ Bt,
    const float* __restrict__ bias, void* __restrict__ out,
    int mode, float scale)
{
    extern __shared__ uint32_t smem[];
    const uint32_t sbase = smem_u32(smem);
    const int tid  = threadIdx.x;
    const int w    = tid >> 5;
    const int lane = tid & 31;
    const int g    = lane >> 2;
    const int tg   = lane & 3;
    const int m0   = blockIdx.y * 128;
    const int n0   = blockIdx.x * 128;
    const int wm   = (w & 1) * 64;
    const int wn   = (w >> 1) * 64;

    float acc[4][8][4];
    #pragma unroll
    for (int i = 0; i < 4; i++)
        #pragma unroll
        for (int j = 0; j < 8; j++)
            #pragma unroll
            for (int r = 0; r < 4; r++) acc[i][j][r] = 0.f;

    gemm_stage(sbase, 0, At, Bt, m0, n0, 0, tid);

    #define NCHUNK 32
    for (int c = 0; c < NCHUNK; c++) {
        const int p = c & 1;
        if (c + 1 < NCHUNK)
            gemm_stage(sbase, p ^ 1, At, Bt, m0, n0, (c + 1) * 32, tid);
        if (c + 1 < NCHUNK) CP_WAIT(1); else CP_WAIT(0);
        __syncthreads();

        const uint32_t* As = smem + (size_t)p * STG_WORDS;
        const uint32_t* Bs = As + AS_WORDS;
        #pragma unroll
        for (int ks = 0; ks < 4; ks++) {
            const int kk = ks * 8;
            uint32_t afr[4][4], bfr[8][2];
            #pragma unroll
            for (int mf = 0; mf < 4; mf++) {
                const int row = wm + mf * 16;
                afr[mf][0] = As[(row + g    ) * ASTR + kk + tg    ];
                afr[mf][1] = As[(row + g + 8) * ASTR + kk + tg    ];
                afr[mf][2] = As[(row + g    ) * ASTR + kk + tg + 4];
                afr[mf][3] = As[(row + g + 8) * ASTR + kk + tg + 4];
            }
            #pragma unroll
            for (int nf = 0; nf < 8; nf++) {
                const int col = wn + nf * 8 + g;
                bfr[nf][0] = Bs[(kk + tg    ) * BSTR + col];
                bfr[nf][1] = Bs[(kk + tg + 4) * BSTR + col];
            }
            #pragma unroll
            for (int mf = 0; mf < 4; mf++)
                #pragma unroll
                for (int nf = 0; nf < 8; nf++)
                    mma_tf32_16x8x8(acc[mf][nf], afr[mf], bfr[nf], acc[mf][nf]);
        }
        __syncthreads();
    }

    #pragma unroll
    for (int mf = 0; mf < 4; mf++) {
        #pragma unroll
        for (int nf = 0; nf < 8; nf++) {
            const int col = n0 + wn + nf * 8 + 2 * tg;
            const float b0 = bias[col], b1 = bias[col + 1];
            #pragma unroll
            for (int half = 0; half < 2; half++) {
                const int m = m0 + wm + mf * 16 + g + half * 8;
                const float v0 = acc[mf][nf][half * 2 + 0] + b0;
                const float v1 = acc[mf][nf][half * 2 + 1] + b1;
                if (mode == 0) {
                    float2* p2 = (float2*)((float*)out + (size_t)m * C_ + col);
                    *p2 = make_float2(v0, v1);
                } else {
                    const int bb = m >> 11;
                    const int t  = m & (T_ - 1);
                    const int h  = col >> 6;
                    const int d  = col & (D_ - 1);
                    uint32_t* p2 = (uint32_t*)out
                        + (((size_t)(bb * H_ + h) * T_ + t) * D_) + d;
                    p2[0] = f2tf32(v0 * scale);
                    p2[1] = f2tf32(v1 * scale);
                }
            }
        }
    }
}

#define QSCALE_ (0.125f * 1.4426950408889634f)

__global__ __launch_bounds__(128)
void qkv_gemm_kernel(const float* __restrict__ bq, const float* __restrict__ bk,
                     const float* __restrict__ bv)
{
    const float* bias; uint32_t* out; float scale;
    if (blockIdx.z == 0)      { bias = bq; out = g_q; scale = QSCALE_; }
    else if (blockIdx.z == 1) { bias = bk; out = g_k; scale = 1.f; }
    else                      { bias = bv; out = g_v; scale = 1.f; }
    gemm_body(g_xt, g_wt[blockIdx.z], bias, out, 1, scale);
}

__global__ __launch_bounds__(128)
void proj_gemm_kernel(const float* __restrict__ bp, float* __restrict__ out)
{
    gemm_body(g_yt, g_wt[3], bp, out, 0, 1.f);
}

// ---------------------------------------------------------------------------
// Flash attention: double-buffered cp.async K/V pipeline + heavy-first order.
// Dynamic SMEM layout (words):
//   stage p (p=0,1): K at p*4352, V at p*4352+2176   (32 x 68 each)
//   Sp at 8704 + w*1152                              (4 x 32 x 36)
// Total = (8704 + 4608) * 4 = 53248 bytes.
// ---------------------------------------------------------------------------
#define KVSTR_ 68
#define PSTR_  36
#define FL_KV_WORDS   (32 * KVSTR_)            // 2176
#define FL_STG_WORDS  (2 * FL_KV_WORDS)        // 4352
#define FL_SP_OFF     (2 * FL_STG_WORDS)       // 8704
#define FL_SMEM_BYTES ((FL_SP_OFF + 4 * 32 * PSTR_) * 4)   // 53248

__device__ __forceinline__ void flash_stage(
    uint32_t sbase, int p, const uint32_t* __restrict__ Kb,
    const uint32_t* __restrict__ Vb, int base, int tid)
{
    const uint32_t ks = sbase + (uint32_t)p * FL_STG_WORDS * 4;
    const uint32_t vs = ks + FL_KV_WORDS * 4;
    #pragma unroll
    for (int i = 0; i < 4; i++) {
        const int e   = tid + i * 128;
        const int key = e >> 4;
        const int c   = (e & 15) * 4;
        cp_async16(ks + (uint32_t)(key * KVSTR_ + c) * 4,
                   Kb + (size_t)(base + key) * D_ + c);
        cp_async16(vs + (uint32_t)(key * KVSTR_ + c) * 4,
                   Vb + (size_t)(base + key) * D_ + c);
    }
    CP_COMMIT();
}

__global__ __launch_bounds__(128)
void flash_tc_kernel()
{
    extern __shared__ uint32_t fsm[];
    const uint32_t sbase = smem_u32(fsm);

    const int bh   = blockIdx.y;
    const int qi   = (T_ / 128 - 1) - blockIdx.x;   // heavy blocks first
    const int tid  = threadIdx.x;
    const int w    = tid >> 5;
    const int lane = tid & 31;
    const int g    = lane >> 2;
    const int tg   = lane & 3;
    const int wrow = qi * 128 + w * 32;

    const uint32_t* Qb = g_q + (size_t)bh * T_ * D_;
    const uint32_t* Kb = g_k + (size_t)bh * T_ * D_;
    const uint32_t* Vb = g_v + (size_t)bh * T_ * D_;
    uint32_t (*Sp)[PSTR_] = (uint32_t (*)[PSTR_])(fsm + FL_SP_OFF + w * 32 * PSTR_);

    // Q fragments (already tf32 bits, already scaled)
    uint32_t qa[2][8][4];
    #pragma unroll
    for (int mf = 0; mf < 2; mf++) {
        const int r0 = wrow + mf * 16 + g;
        const int r1 = r0 + 8;
        #pragma unroll
        for (int ks = 0; ks < 8; ks++) {
            qa[mf][ks][0] = Qb[(size_t)r0 * D_ + ks * 8 + tg    ];
            qa[mf][ks][1] = Qb[(size_t)r1 * D_ + ks * 8 + tg    ];
            qa[mf][ks][2] = Qb[(size_t)r0 * D_ + ks * 8 + tg + 4];
            qa[mf][ks][3] = Qb[(size_t)r1 * D_ + ks * 8 + tg + 4];
        }
    }

    float onf[2][8][4];
    #pragma unroll
    for (int mf = 0; mf < 2; mf++)
        #pragma unroll
        for (int nf = 0; nf < 8; nf++)
            #pragma unroll
            for (int c = 0; c < 4; c++) onf[mf][nf][c] = 0.f;
    float mrow[2][2] = {{-1e30f, -1e30f}, {-1e30f, -1e30f}};
    float lrow[2][2] = {{0.f, 0.f}, {0.f, 0.f}};

    const int ntile   = 4 * (qi + 1);
    const int maskBeg = 4 * qi;

    flash_stage(sbase, 0, Kb, Vb, 0, tid);

    for (int jt = 0; jt < ntile; jt++) {
        const int p = jt & 1;
        if (jt + 1 < ntile) {
            flash_stage(sbase, p ^ 1, Kb, Vb, (jt + 1) * 32, tid);
            CP_WAIT(1);
        } else {
            CP_WAIT(0);
        }
        __syncthreads();

        const uint32_t (*Kt)[KVSTR_] =
            (const uint32_t (*)[KVSTR_])(fsm + p * FL_STG_WORDS);
        const uint32_t (*Vt)[KVSTR_] =
            (const uint32_t (*)[KVSTR_])(fsm + p * FL_STG_WORDS + FL_KV_WORDS);
        const int base = jt * 32;

        // QK^T
        float s[2][4][4];
        #pragma unroll
        for (int mf = 0; mf < 2; mf++)
            #pragma unroll
            for (int nf = 0; nf < 4; nf++)
                #pragma unroll
                for (int c = 0; c < 4; c++) s[mf][nf][c] = 0.f;

        #pragma unroll
        for (int nf = 0; nf < 4; nf++) {
            #pragma unroll
            for (int ks = 0; ks < 8; ks++) {
                uint32_t b[2];
                b[0] = Kt[nf * 8 + g][ks * 8 + tg    ];
                b[1] = Kt[nf * 8 + g][ks * 8 + tg + 4];
                mma_tf32_16x8x8(s[0][nf], qa[0][ks], b, s[0][nf]);
                mma_tf32_16x8x8(s[1][nf], qa[1][ks], b, s[1][nf]);
            }
        }

        if (jt >= maskBeg) {
            #pragma unroll
            for (int mf = 0; mf < 2; mf++)
                #pragma unroll
                for (int nf = 0; nf < 4; nf++)
                    #pragma unroll
                    for (int c = 0; c < 4; c++) {
                        const int row = wrow + mf * 16 + g + (c >> 1) * 8;
                        const int col = base + nf * 8 + 2 * tg + (c & 1);
                        if (col > row) s[mf][nf][c] = -1e30f;
                    }
        }

        // online softmax (base-2)
        #pragma unroll
        for (int mf = 0; mf < 2; mf++) {
            #pragma unroll
            for (int h = 0; h < 2; h++) {
                float rmax = -1e30f;
                #pragma unroll
                for (int nf = 0; nf < 4; nf++)
                    rmax = fmaxf(rmax, fmaxf(s[mf][nf][h * 2], s[mf][nf][h * 2 + 1]));
                rmax = fmaxf(rmax, __shfl_xor_sync(0xffffffffu, rmax, 1));
                rmax = fmaxf(rmax, __shfl_xor_sync(0xffffffffu, rmax, 2));

                const float mnew = fmaxf(mrow[mf][h], rmax);
                const float corr = fexp2(mrow[mf][h] - mnew);
                mrow[mf][h] = mnew;

                float rsum = 0.f;
                #pragma unroll
                for (int nf = 0; nf < 4; nf++) {
                    float p0 = fexp2(s[mf][nf][h * 2    ] - mnew);
                    float p1 = fexp2(s[mf][nf][h * 2 + 1] - mnew);
                    s[mf][nf][h * 2    ] = p0;
                    s[mf][nf][h * 2 + 1] = p1;
                    rsum += p0 + p1;
                }
                rsum += __shfl_xor_sync(0xffffffffu, rsum, 1);
                rsum += __shfl_xor_sync(0xffffffffu, rsum, 2);
                lrow[mf][h] = lrow[mf][h] * corr + rsum;

                #pragma unroll
                for (int nf = 0; nf < 8; nf++) {
                    onf[mf][nf][h * 2    ] *= corr;
                    onf[mf][nf][h * 2 + 1] *= corr;
                }
            }
        }

        // stage P (tf32 bits) for A-operand layout
        __syncwarp();
        #pragma unroll
        for (int mf = 0; mf < 2; mf++)
            #pragma unroll
            for (int nf = 0; nf < 4; nf++) {
                Sp[mf * 16 + g    ][nf * 8 + 2 * tg    ] = f2tf32(s[mf][nf][0]);
                Sp[mf * 16 + g    ][nf * 8 + 2 * tg + 1] = f2tf32(s[mf][nf][1]);
                Sp[mf * 16 + g + 8][nf * 8 + 2 * tg    ] = f2tf32(s[mf][nf][2]);
                Sp[mf * 16 + g + 8][nf * 8 + 2 * tg + 1] = f2tf32(s[mf][nf][3]);
            }
        __syncwarp();

        // P @ V
        #pragma unroll
        for (int pk = 0; pk < 4; pk++) {
            uint32_t a0[4], a1[4];
            a0[0] = Sp[g     ][pk * 8 + tg    ];
            a0[1] = Sp[g + 8 ][pk * 8 + tg    ];
            a0[2] = Sp[g     ][pk * 8 + tg + 4];
            a0[3] = Sp[g + 8 ][pk * 8 + tg + 4];
            a1[0] = Sp[g + 16][pk * 8 + tg    ];
            a1[1] = Sp[g + 24][pk * 8 + tg    ];
            a1[2] = Sp[g + 16][pk * 8 + tg + 4];
            a1[3] = Sp[g + 24][pk * 8 + tg + 4];
            #pragma unroll
            for (int nf = 0; nf < 8; nf++) {
                uint32_t b[2];
                b[0] = Vt[pk * 8 + tg    ][nf * 8 + g];
                b[1] = Vt[pk * 8 + tg + 4][nf * 8 + g];
                mma_tf32_16x8x8(onf[0][nf], a0, b, onf[0][nf]);
                mma_tf32_16x8x8(onf[1][nf], a1, b, onf[1][nf]);
            }
        }
        __syncthreads();
    }

    // normalize, convert to tf32 bits, write to g_yt
    const int b  = bh >> 4;
    const int hh = bh & (H_ - 1);
    #pragma unroll
    for (int mf = 0; mf < 2; mf++) {
        const float inv0 = 1.f / lrow[mf][0];
        const float inv1 = 1.f / lrow[mf][1];
        const int r0 = wrow + mf * 16 + g;
        #pragma unroll
        for (int nf = 0; nf < 8; nf++) {
            const int d = nf * 8 + 2 * tg;
            uint32_t* p0 = &g_yt[((size_t)(b * T_ + r0) * C_) + hh * D_ + d];
            p0[0] = f2tf32(onf[mf][nf][0] * inv0);
            p0[1] = f2tf32(onf[mf][nf][1] * inv0);
            uint32_t* p1 = &g_yt[((size_t)(b * T_ + r0 + 8) * C_) + hh * D_ + d];
            p1[0] = f2tf32(onf[mf][nf][2] * inv1);
            p1[1] = f2tf32(onf[mf][nf][3] * inv1);
        }
    }
}

// ---------------------------------------------------------------------------
extern "C" void kernel_launch(void* const* d_in, const int* in_sizes, int n_in,
                              void* d_out, int out_size)
{
    const float* x  = (const float*)d_in[0];
    const float* Wq = (const float*)d_in[1];
    const float* bq = (const float*)d_in[2];
    const float* Wk = (const float*)d_in[3];
    const float* bk = (const float*)d_in[4];
    const float* Wv = (const float*)d_in[5];
    const float* bv = (const float*)d_in[6];
    const float* Wp = (const float*)d_in[7];
    const float* bp = (const float*)d_in[8];
    float* out = (float*)d_out;

    cudaFuncSetAttribute(qkv_gemm_kernel,
                         cudaFuncAttributeMaxDynamicSharedMemorySize, GSMEM_BYTES);
    cudaFuncSetAttribute(proj_gemm_kernel,
                         cudaFuncAttributeMaxDynamicSharedMemorySize, GSMEM_BYTES);
    cudaFuncSetAttribute(flash_tc_kernel,
                         cudaFuncAttributeMaxDynamicSharedMemorySize, FL_SMEM_BYTES);

    const int wn4 = (C_ * C_) / 4;
    dim3 gw(wn4 / 256, 1, 4);
    cvt_w_kernel<<<gw, 256>>>((const float4*)Wq, (const float4*)Wk,
                              (const float4*)Wv, (const float4*)Wp);
    const int xn4 = (M_ * C_) / 4;
    cvt_x_kernel<<<xn4 / 256, 256>>>((const float4*)x);

    dim3 gq(C_ / 128, M_ / 128, 3);
    qkv_gemm_kernel<<<gq, 128, GSMEM_BYTES>>>(bq, bk, bv);

    dim3 gf(T_ / 128, B_ * H_);
    flash_tc_kernel<<<gf, 128, FL_SMEM_BYTES>>>();

    dim3 gp(C_ / 128, M_ / 128);
    proj_gemm_kernel<<<gp, 128, GSMEM_BYTES>>>(bp, out);
}